// round 1
// baseline (speedup 1.0000x reference)
#include <cuda_runtime.h>
#include <math.h>

#define NN 65536
#define EE 1048576
#define DD 512
#define BB 64

// ---------------- scratch (device globals; no allocations) ----------------
__device__ float    g_mean[2][NN];
__device__ float    g_rstd[2][NN];
__device__ float    g_k[2][NN];
__device__ float    g_q[2][NN];
__device__ float    g_v[2][NN];
__device__ unsigned g_m[2][NN];        // ordered-uint encoded segment max
__device__ float    g_s[2][NN];        // sum of exp
__device__ float    g_t[2][NN];        // sum of exp * vt
__device__ float    g_score[2][NN];
__device__ unsigned g_bmax[2][BB];     // ordered-uint batch max of score
__device__ float    g_bsum[2][BB];
__device__ int      g_start[2][BB + 1];
__device__ float    g_add[2][BB * DD];
__device__ float    g_maxp[2][BB * DD];

// ordered-uint float encoding: monotonic w.r.t. float order, usable with atomicMax
__device__ __forceinline__ unsigned fenc(float f) {
    unsigned u = __float_as_uint(f);
    return (u & 0x80000000u) ? ~u : (u | 0x80000000u);
}
__device__ __forceinline__ float fdec(unsigned u) {
    return (u & 0x80000000u) ? __uint_as_float(u & 0x7FFFFFFFu)
                             : __uint_as_float(~u);
}

// ---------------- init ----------------
__global__ void k_init() {
    int i = blockIdx.x * 256 + threadIdx.x;
    if (i < NN) {
        #pragma unroll
        for (int t = 0; t < 2; t++) {
            g_m[t][i] = 0x007FFFFFu;   // fenc(-inf)
            g_s[t][i] = 0.f;
            g_t[t][i] = 0.f;
        }
    }
    if (i < BB) {
        #pragma unroll
        for (int t = 0; t < 2; t++) {
            g_bmax[t][i] = 0x007FFFFFu;
            g_bsum[t][i] = 0.f;
        }
    }
}

// ---------------- LayerNorm + kqv projection (scalar k,q,v per node) ------
// one block (128 threads, float4 each) per row
__global__ void k_ln_kqv(const float* __restrict__ x,
                         const float* __restrict__ g,
                         const float* __restrict__ be,
                         const float* __restrict__ W,     // (D,3) row-major
                         const float* __restrict__ bk,    // (3,)
                         int t) {
    __shared__ float sW[DD * 3];
    __shared__ float rs[4], rss[4];
    __shared__ float rd[3][4];

    int row = blockIdx.x;
    int tid = threadIdx.x;
    for (int i = tid; i < DD * 3; i += 128) sW[i] = W[i];

    const float4* xr = reinterpret_cast<const float4*>(x + (size_t)row * DD);
    float4 xv = xr[tid];
    float s  = xv.x + xv.y + xv.z + xv.w;
    float ss = xv.x * xv.x + xv.y * xv.y + xv.z * xv.z + xv.w * xv.w;
    #pragma unroll
    for (int o = 16; o; o >>= 1) {
        s  += __shfl_xor_sync(0xffffffffu, s, o);
        ss += __shfl_xor_sync(0xffffffffu, ss, o);
    }
    int w = tid >> 5, l = tid & 31;
    if (l == 0) { rs[w] = s; rss[w] = ss; }
    __syncthreads();
    float tot  = rs[0] + rs[1] + rs[2] + rs[3];
    float tots = rss[0] + rss[1] + rss[2] + rss[3];
    float m   = tot * (1.f / DD);
    float var = tots * (1.f / DD) - m * m;
    float r   = rsqrtf(var + 1e-5f);

    const float4* gr = reinterpret_cast<const float4*>(g);
    const float4* br = reinterpret_cast<const float4*>(be);
    float4 gv = gr[tid], bv = br[tid];
    float xn0 = (xv.x - m) * r * gv.x + bv.x;
    float xn1 = (xv.y - m) * r * gv.y + bv.y;
    float xn2 = (xv.z - m) * r * gv.z + bv.z;
    float xn3 = (xv.w - m) * r * gv.w + bv.w;

    int base = tid * 12;   // 4 rows * 3 cols
    float d0 = xn0 * sW[base + 0] + xn1 * sW[base + 3] + xn2 * sW[base + 6] + xn3 * sW[base + 9];
    float d1 = xn0 * sW[base + 1] + xn1 * sW[base + 4] + xn2 * sW[base + 7] + xn3 * sW[base + 10];
    float d2 = xn0 * sW[base + 2] + xn1 * sW[base + 5] + xn2 * sW[base + 8] + xn3 * sW[base + 11];
    #pragma unroll
    for (int o = 16; o; o >>= 1) {
        d0 += __shfl_xor_sync(0xffffffffu, d0, o);
        d1 += __shfl_xor_sync(0xffffffffu, d1, o);
        d2 += __shfl_xor_sync(0xffffffffu, d2, o);
    }
    if (l == 0) { rd[0][w] = d0; rd[1][w] = d1; rd[2][w] = d2; }
    __syncthreads();
    if (tid == 0) {
        float D0 = rd[0][0] + rd[0][1] + rd[0][2] + rd[0][3];
        float D1 = rd[1][0] + rd[1][1] + rd[1][2] + rd[1][3];
        float D2 = rd[2][0] + rd[2][1] + rd[2][2] + rd[2][3];
        g_k[t][row]    = D0 + bk[0];
        g_q[t][row]    = D1 + bk[1];
        g_v[t][row]    = D2 + bk[2];
        g_mean[t][row] = m;
        g_rstd[t][row] = r;
    }
}

// ---------------- batch segment start offsets (batch is sorted) -----------
__global__ void k_starts(const int* __restrict__ batch, int t) {
    int i = blockIdx.x * 256 + threadIdx.x;
    if (i >= NN) return;
    int b = batch[i];
    int prev = (i == 0) ? -1 : batch[i - 1];
    for (int bb = prev + 1; bb <= b; bb++) g_start[t][bb] = i;
    if (i == NN - 1) {
        for (int bb = b + 1; bb <= BB; bb++) g_start[t][bb] = NN;
    }
}

// ---------------- edge attention: pass 1, segment max ---------------------
__global__ void k_edge_max(const int* __restrict__ ei,
                           const float* __restrict__ krw,
                           const float* __restrict__ krb,
                           const float* __restrict__ prel,
                           int rel, int tsrc, int tdst) {
    int e = blockIdx.x * 256 + threadIdx.x;
    int s = ei[e];
    int d = ei[EE + e];
    float kt = g_k[tsrc][s] * krw[rel] + krb[rel];
    float logit = g_q[tdst][d] * kt * prel[rel];
    atomicMax(&g_m[tdst][d], fenc(logit));
}

// ---------------- edge attention: pass 2, exp sums ------------------------
__global__ void k_edge_sum(const int* __restrict__ ei,
                           const float* __restrict__ krw,
                           const float* __restrict__ krb,
                           const float* __restrict__ vrw,
                           const float* __restrict__ vrb,
                           const float* __restrict__ prel,
                           int rel, int tsrc, int tdst) {
    int e = blockIdx.x * 256 + threadIdx.x;
    int s = ei[e];
    int d = ei[EE + e];
    float kt = g_k[tsrc][s] * krw[rel] + krb[rel];
    float vt = g_v[tsrc][s] * vrw[rel] + vrb[rel];
    float logit = g_q[tdst][d] * kt * prel[rel];
    float ex = expf(logit - fdec(g_m[tdst][d]));
    atomicAdd(&g_s[tdst][d], ex);
    atomicAdd(&g_t[tdst][d], ex * vt);
}

// ---------------- score = gelu(aggr*w+b); batch max (warp-aggregated) -----
__global__ void k_score(const float* __restrict__ wout,
                        const float* __restrict__ bout,
                        const int* __restrict__ batch, int t) {
    int n = blockIdx.x * 256 + threadIdx.x;
    float ssum = g_s[t][n];
    float aggr = (ssum > 0.f) ? g_t[t][n] / ssum : 0.f;
    float xx = aggr * wout[0] + bout[0];
    float sc = 0.5f * xx * (1.f + erff(xx * 0.7071067811865475f));
    g_score[t][n] = sc;
    int b = batch[n];
    int b0 = __shfl_sync(0xffffffffu, b, 0);
    if (__all_sync(0xffffffffu, b == b0)) {
        float mv = sc;
        #pragma unroll
        for (int o = 16; o; o >>= 1) mv = fmaxf(mv, __shfl_xor_sync(0xffffffffu, mv, o));
        if ((threadIdx.x & 31) == 0) atomicMax(&g_bmax[t][b], fenc(mv));
    } else {
        atomicMax(&g_bmax[t][b], fenc(sc));
    }
}

// ---------------- batch softmax denominator -------------------------------
__global__ void k_bsum(const int* __restrict__ batch, int t) {
    int n = blockIdx.x * 256 + threadIdx.x;
    int b = batch[n];
    float ev = expf(g_score[t][n] - fdec(g_bmax[t][b]));
    int b0 = __shfl_sync(0xffffffffu, b, 0);
    if (__all_sync(0xffffffffu, b == b0)) {
        float sv = ev;
        #pragma unroll
        for (int o = 16; o; o >>= 1) sv += __shfl_xor_sync(0xffffffffu, sv, o);
        if ((threadIdx.x & 31) == 0) atomicAdd(&g_bsum[t][b], sv);
    } else {
        atomicAdd(&g_bsum[t][b], ev);
    }
}

// ---------------- pooling: per-batch weighted sum + max of xn -------------
// block = (batch, 128-col chunk); iterates the sorted batch segment
__global__ void k_pool(const float* __restrict__ x,
                       const float* __restrict__ g,
                       const float* __restrict__ be,
                       int t) {
    int b     = blockIdx.x >> 2;
    int chunk = blockIdx.x & 3;
    int col   = chunk * 128 + threadIdx.x;
    float gv  = g[col];
    float bev = be[col];
    float bm    = fdec(g_bmax[t][b]);
    float bsinv = 1.f / g_bsum[t][b];
    int s0 = g_start[t][b], s1 = g_start[t][b + 1];

    float acc = 0.f;
    float mx  = -INFINITY;
    int n = s0;
    for (; n + 8 <= s1; n += 8) {
        float xv[8], sn[8], mn[8], cf[8];
        #pragma unroll
        for (int u = 0; u < 8; u++) xv[u] = x[(size_t)(n + u) * DD + col];
        #pragma unroll
        for (int u = 0; u < 8; u++) {
            sn[u] = expf(g_score[t][n + u] - bm) * bsinv;
            mn[u] = g_mean[t][n + u];
            cf[u] = g_rstd[t][n + u] * sn[u];
        }
        #pragma unroll
        for (int u = 0; u < 8; u++) {
            float xw = (xv[u] - mn[u]) * cf[u] * gv + bev * sn[u];
            acc += xw;
            mx = fmaxf(mx, xw);
        }
    }
    for (; n < s1; n++) {
        float snv = expf(g_score[t][n] - bm) * bsinv;
        float xw = (x[(size_t)n * DD + col] - g_mean[t][n]) * g_rstd[t][n] * snv * gv + bev * snv;
        acc += xw;
        mx = fmaxf(mx, xw);
    }
    g_add[t][b * DD + col]  = acc;
    g_maxp[t][b * DD + col] = mx;
}

// ---------------- final MLP: (B, 2D) @ (2D, D) + b ------------------------
// grid.x = 4 (128-col chunks), grid.y = 8 (8 batches per block)
__global__ void k_mlp(const float* __restrict__ W,
                      const float* __restrict__ bmlp,
                      float* __restrict__ out, int t) {
    __shared__ float cat[8 * 1024];
    int dchunk = blockIdx.x;
    int bg     = blockIdx.y;
    for (int i = threadIdx.x; i < 8 * 1024; i += 128) {
        int bb = i >> 10;
        int k  = i & 1023;
        int gb = bg * 8 + bb;
        cat[i] = (k < DD) ? g_add[t][gb * DD + k] : g_maxp[t][gb * DD + (k - DD)];
    }
    __syncthreads();

    int col = dchunk * 128 + threadIdx.x;
    float acc[8];
    #pragma unroll
    for (int bb = 0; bb < 8; bb++) acc[bb] = 0.f;

    const float4* cat4 = reinterpret_cast<const float4*>(cat);
    for (int k = 0; k < 1024; k += 4) {
        float w0 = W[(k + 0) * DD + col];
        float w1 = W[(k + 1) * DD + col];
        float w2 = W[(k + 2) * DD + col];
        float w3 = W[(k + 3) * DD + col];
        #pragma unroll
        for (int bb = 0; bb < 8; bb++) {
            float4 c = cat4[(bb * 1024 + k) >> 2];
            acc[bb] += c.x * w0 + c.y * w1 + c.z * w2 + c.w * w3;
        }
    }
    float bias = bmlp[col];
    #pragma unroll
    for (int bb = 0; bb < 8; bb++) {
        int gb = bg * 8 + bb;
        out[gb * (2 * DD) + t * DD + col] = acc[bb] + bias;
    }
}

// ---------------- launch ---------------------------------------------------
extern "C" void kernel_launch(void* const* d_in, const int* in_sizes, int n_in,
                              void* d_out, int out_size) {
    const float* x_inst     = (const float*)d_in[0];
    const float* x_net      = (const float*)d_in[1];
    const float* ln_g_inst  = (const float*)d_in[2];
    const float* ln_b_inst  = (const float*)d_in[3];
    const float* ln_g_net   = (const float*)d_in[4];
    const float* ln_b_net   = (const float*)d_in[5];
    const float* Wkqv_inst  = (const float*)d_in[6];
    const float* bkqv_inst  = (const float*)d_in[7];
    const float* Wkqv_net   = (const float*)d_in[8];
    const float* bkqv_net   = (const float*)d_in[9];
    const float* k_rel_w    = (const float*)d_in[10];
    const float* k_rel_b    = (const float*)d_in[11];
    const float* v_rel_w    = (const float*)d_in[12];
    const float* v_rel_b    = (const float*)d_in[13];
    const float* p_rel      = (const float*)d_in[14];
    const float* w_out_inst = (const float*)d_in[15];
    const float* b_out_inst = (const float*)d_in[16];
    const float* w_out_net  = (const float*)d_in[17];
    const float* b_out_net  = (const float*)d_in[18];
    const float* W_mlp_inst = (const float*)d_in[19];
    const float* b_mlp_inst = (const float*)d_in[20];
    const float* W_mlp_net  = (const float*)d_in[21];
    const float* b_mlp_net  = (const float*)d_in[22];
    const int*   ei_i2n     = (const int*)d_in[23];
    const int*   ei_n2i     = (const int*)d_in[24];
    const int*   batch_inst = (const int*)d_in[25];
    const int*   batch_net  = (const int*)d_in[26];
    float* out = (float*)d_out;

    k_init<<<NN / 256, 256>>>();

    k_ln_kqv<<<NN, 128>>>(x_inst, ln_g_inst, ln_b_inst, Wkqv_inst, bkqv_inst, 0);
    k_ln_kqv<<<NN, 128>>>(x_net,  ln_g_net,  ln_b_net,  Wkqv_net,  bkqv_net,  1);

    k_starts<<<NN / 256, 256>>>(batch_inst, 0);
    k_starts<<<NN / 256, 256>>>(batch_net, 1);

    // dir 0: inst -> net  (src=inst(0), dst=net(1), rel=0)
    // dir 1: net -> inst  (src=net(1),  dst=inst(0), rel=1)
    k_edge_max<<<EE / 256, 256>>>(ei_i2n, k_rel_w, k_rel_b, p_rel, 0, 0, 1);
    k_edge_max<<<EE / 256, 256>>>(ei_n2i, k_rel_w, k_rel_b, p_rel, 1, 1, 0);
    k_edge_sum<<<EE / 256, 256>>>(ei_i2n, k_rel_w, k_rel_b, v_rel_w, v_rel_b, p_rel, 0, 0, 1);
    k_edge_sum<<<EE / 256, 256>>>(ei_n2i, k_rel_w, k_rel_b, v_rel_w, v_rel_b, p_rel, 1, 1, 0);

    k_score<<<NN / 256, 256>>>(w_out_inst, b_out_inst, batch_inst, 0);
    k_score<<<NN / 256, 256>>>(w_out_net,  b_out_net,  batch_net,  1);
    k_bsum<<<NN / 256, 256>>>(batch_inst, 0);
    k_bsum<<<NN / 256, 256>>>(batch_net, 1);

    k_pool<<<BB * 4, 128>>>(x_inst, ln_g_inst, ln_b_inst, 0);
    k_pool<<<BB * 4, 128>>>(x_net,  ln_g_net,  ln_b_net,  1);

    k_mlp<<<dim3(4, 8), 128>>>(W_mlp_inst, b_mlp_inst, out, 0);
    k_mlp<<<dim3(4, 8), 128>>>(W_mlp_net,  b_mlp_net,  out, 1);
}

// round 2
// speedup vs baseline: 3.0919x; 3.0919x over previous
#include <cuda_runtime.h>
#include <math.h>

#define NN 65536
#define EE 1048576
#define DD 512
#define BB 64
#define SL 16   // pool slices per batch
#define KS 4    // mlp k-splits

// ---------------- scratch (device globals; no allocations) ----------------
__device__ float    g_mean[2][NN];
__device__ float    g_rstd[2][NN];
__device__ float    g_kt[2][NN];     // k * k_rel_w[rel_src] + k_rel_b[rel_src]
__device__ float    g_qp[2][NN];     // q * p_rel[rel_dst]
__device__ float    g_vt[2][NN];     // v * v_rel_w[rel_src] + v_rel_b[rel_src]
__device__ unsigned g_m[2][NN];      // ordered-uint segment max of logits
__device__ float    g_s[2][NN];      // sum exp
__device__ float    g_t[2][NN];      // sum exp * vt
__device__ float    g_score[2][NN];
__device__ float    g_sn[2][NN];     // batch-softmax weight per node
__device__ unsigned g_bmax[2][BB];
__device__ float    g_bsum[2][BB];
__device__ int      g_start[2][BB + 1];
__device__ float    g_padd[2][BB][SL][DD];
__device__ float    g_pmax[2][BB][SL][DD];
__device__ float    g_add[2][BB][DD];
__device__ float    g_maxp[2][BB][DD];
__device__ float    g_mpart[2][KS][BB][DD];

__device__ __forceinline__ unsigned fenc(float f) {
    unsigned u = __float_as_uint(f);
    return (u & 0x80000000u) ? ~u : (u | 0x80000000u);
}
__device__ __forceinline__ float fdec(unsigned u) {
    return (u & 0x80000000u) ? __uint_as_float(u & 0x7FFFFFFFu)
                             : __uint_as_float(~u);
}

// ---------------- init ----------------
__global__ void k_init() {
    int i = blockIdx.x * 256 + threadIdx.x;
    if (i < NN) {
        #pragma unroll
        for (int t = 0; t < 2; t++) {
            g_m[t][i] = 0x007FFFFFu;   // fenc(-inf)
            g_s[t][i] = 0.f;
            g_t[t][i] = 0.f;
        }
    }
    if (i < BB) {
        #pragma unroll
        for (int t = 0; t < 2; t++) {
            g_bmax[t][i] = 0x007FFFFFu;
            g_bsum[t][i] = 0.f;
        }
    }
}

// ---------------- LayerNorm + kqv projection: warp-per-row ----------------
// block = 256 threads = 8 warps = 8 rows; grid = NN/8
__global__ void k_ln_kqv(const float* __restrict__ x,
                         const float* __restrict__ g,
                         const float* __restrict__ be,
                         const float* __restrict__ W,     // (D,3) row-major
                         const float* __restrict__ bk,    // (3,)
                         const float* __restrict__ krw,
                         const float* __restrict__ krb,
                         const float* __restrict__ vrw,
                         const float* __restrict__ vrb,
                         const float* __restrict__ prel,
                         int t) {
    __shared__ float sWT[3][DD];     // transposed: sWT[j][c] = W[c*3+j]
    int tid = threadIdx.x;
    for (int i = tid; i < DD * 3; i += 256) sWT[i % 3][i / 3] = W[i];
    __syncthreads();

    int warp = tid >> 5, lane = tid & 31;
    int row  = blockIdx.x * 8 + warp;

    const float4* xr = reinterpret_cast<const float4*>(x + (size_t)row * DD);
    float4 xv[4];
    #pragma unroll
    for (int j = 0; j < 4; j++) xv[j] = xr[lane + 32 * j];

    float s = 0.f, ss = 0.f;
    #pragma unroll
    for (int j = 0; j < 4; j++) {
        s  += xv[j].x + xv[j].y + xv[j].z + xv[j].w;
        ss += xv[j].x * xv[j].x + xv[j].y * xv[j].y
            + xv[j].z * xv[j].z + xv[j].w * xv[j].w;
    }
    #pragma unroll
    for (int o = 16; o; o >>= 1) {
        s  += __shfl_xor_sync(0xffffffffu, s, o);
        ss += __shfl_xor_sync(0xffffffffu, ss, o);
    }
    float m   = s * (1.f / DD);
    float var = ss * (1.f / DD) - m * m;
    float r   = rsqrtf(var + 1e-5f);

    const float4* gr = reinterpret_cast<const float4*>(g);
    const float4* br = reinterpret_cast<const float4*>(be);
    const float4* w0p = reinterpret_cast<const float4*>(sWT[0]);
    const float4* w1p = reinterpret_cast<const float4*>(sWT[1]);
    const float4* w2p = reinterpret_cast<const float4*>(sWT[2]);

    float d0 = 0.f, d1 = 0.f, d2 = 0.f;
    #pragma unroll
    for (int j = 0; j < 4; j++) {
        int idx = lane + 32 * j;
        float4 gv = gr[idx], bv = br[idx];
        float x0 = (xv[j].x - m) * r * gv.x + bv.x;
        float x1 = (xv[j].y - m) * r * gv.y + bv.y;
        float x2 = (xv[j].z - m) * r * gv.z + bv.z;
        float x3 = (xv[j].w - m) * r * gv.w + bv.w;
        float4 w0 = w0p[idx], w1 = w1p[idx], w2 = w2p[idx];
        d0 += x0 * w0.x + x1 * w0.y + x2 * w0.z + x3 * w0.w;
        d1 += x0 * w1.x + x1 * w1.y + x2 * w1.z + x3 * w1.w;
        d2 += x0 * w2.x + x1 * w2.y + x2 * w2.z + x3 * w2.w;
    }
    #pragma unroll
    for (int o = 16; o; o >>= 1) {
        d0 += __shfl_xor_sync(0xffffffffu, d0, o);
        d1 += __shfl_xor_sync(0xffffffffu, d1, o);
        d2 += __shfl_xor_sync(0xffffffffu, d2, o);
    }
    if (lane == 0) {
        float kk = d0 + bk[0];
        float qq = d1 + bk[1];
        float vv = d2 + bk[2];
        g_kt[t][row]   = kk * krw[t] + krb[t];       // src rel = t
        g_qp[t][row]   = qq * prel[1 - t];           // dst rel = 1-t
        g_vt[t][row]   = vv * vrw[t] + vrb[t];
        g_mean[t][row] = m;
        g_rstd[t][row] = r;
    }
}

// ---------------- batch segment start offsets (batch is sorted) -----------
__global__ void k_starts(const int* __restrict__ batch, int t) {
    int i = blockIdx.x * 256 + threadIdx.x;
    if (i >= NN) return;
    int b = batch[i];
    int prev = (i == 0) ? -1 : batch[i - 1];
    for (int bb = prev + 1; bb <= b; bb++) g_start[t][bb] = i;
    if (i == NN - 1) {
        for (int bb = b + 1; bb <= BB; bb++) g_start[t][bb] = NN;
    }
}

// ---------------- edge pass 1: segment max (both dirs, 4 edges/thread) ----
__global__ void k_edge_max(const int* __restrict__ ei0,
                           const int* __restrict__ ei1) {
    int dir = blockIdx.y;
    const int* ei = dir ? ei1 : ei0;
    int ts = dir, td = 1 - dir;
    int e4 = blockIdx.x * 256 + threadIdx.x;
    int4 s4 = reinterpret_cast<const int4*>(ei)[e4];
    int4 d4 = reinterpret_cast<const int4*>(ei + EE)[e4];
    float l0 = g_qp[td][d4.x] * g_kt[ts][s4.x];
    float l1 = g_qp[td][d4.y] * g_kt[ts][s4.y];
    float l2 = g_qp[td][d4.z] * g_kt[ts][s4.z];
    float l3 = g_qp[td][d4.w] * g_kt[ts][s4.w];
    atomicMax(&g_m[td][d4.x], fenc(l0));
    atomicMax(&g_m[td][d4.y], fenc(l1));
    atomicMax(&g_m[td][d4.z], fenc(l2));
    atomicMax(&g_m[td][d4.w], fenc(l3));
}

// ---------------- edge pass 2: exp sums ------------------------------------
__global__ void k_edge_sum(const int* __restrict__ ei0,
                           const int* __restrict__ ei1) {
    int dir = blockIdx.y;
    const int* ei = dir ? ei1 : ei0;
    int ts = dir, td = 1 - dir;
    int e4 = blockIdx.x * 256 + threadIdx.x;
    int4 s4 = reinterpret_cast<const int4*>(ei)[e4];
    int4 d4 = reinterpret_cast<const int4*>(ei + EE)[e4];
    {
        float ex = expf(g_qp[td][d4.x] * g_kt[ts][s4.x] - fdec(g_m[td][d4.x]));
        atomicAdd(&g_s[td][d4.x], ex);
        atomicAdd(&g_t[td][d4.x], ex * g_vt[ts][s4.x]);
    }
    {
        float ex = expf(g_qp[td][d4.y] * g_kt[ts][s4.y] - fdec(g_m[td][d4.y]));
        atomicAdd(&g_s[td][d4.y], ex);
        atomicAdd(&g_t[td][d4.y], ex * g_vt[ts][s4.y]);
    }
    {
        float ex = expf(g_qp[td][d4.z] * g_kt[ts][s4.z] - fdec(g_m[td][d4.z]));
        atomicAdd(&g_s[td][d4.z], ex);
        atomicAdd(&g_t[td][d4.z], ex * g_vt[ts][s4.z]);
    }
    {
        float ex = expf(g_qp[td][d4.w] * g_kt[ts][s4.w] - fdec(g_m[td][d4.w]));
        atomicAdd(&g_s[td][d4.w], ex);
        atomicAdd(&g_t[td][d4.w], ex * g_vt[ts][s4.w]);
    }
}

// ---------------- score = gelu(aggr*w+b); batch max ------------------------
__global__ void k_score(const float* __restrict__ wout,
                        const float* __restrict__ bout,
                        const int* __restrict__ batch, int t) {
    int n = blockIdx.x * 256 + threadIdx.x;
    float ssum = g_s[t][n];
    float aggr = (ssum > 0.f) ? g_t[t][n] / ssum : 0.f;
    float xx = aggr * wout[0] + bout[0];
    float sc = 0.5f * xx * (1.f + erff(xx * 0.7071067811865475f));
    g_score[t][n] = sc;
    int b = batch[n];
    int b0 = __shfl_sync(0xffffffffu, b, 0);
    if (__all_sync(0xffffffffu, b == b0)) {
        float mv = sc;
        #pragma unroll
        for (int o = 16; o; o >>= 1) mv = fmaxf(mv, __shfl_xor_sync(0xffffffffu, mv, o));
        if ((threadIdx.x & 31) == 0) atomicMax(&g_bmax[t][b], fenc(mv));
    } else {
        atomicMax(&g_bmax[t][b], fenc(sc));
    }
}

// ---------------- batch softmax denominator --------------------------------
__global__ void k_bsum(const int* __restrict__ batch, int t) {
    int n = blockIdx.x * 256 + threadIdx.x;
    int b = batch[n];
    float ev = expf(g_score[t][n] - fdec(g_bmax[t][b]));
    int b0 = __shfl_sync(0xffffffffu, b, 0);
    if (__all_sync(0xffffffffu, b == b0)) {
        float sv = ev;
        #pragma unroll
        for (int o = 16; o; o >>= 1) sv += __shfl_xor_sync(0xffffffffu, sv, o);
        if ((threadIdx.x & 31) == 0) atomicAdd(&g_bsum[t][b], sv);
    } else {
        atomicAdd(&g_bsum[t][b], ev);
    }
}

// ---------------- per-node softmax weight ----------------------------------
__global__ void k_sn(const int* __restrict__ batch0,
                     const int* __restrict__ batch1) {
    int t = blockIdx.y;
    const int* batch = t ? batch1 : batch0;
    int n = blockIdx.x * 256 + threadIdx.x;
    int b = batch[n];
    g_sn[t][n] = expf(g_score[t][n] - fdec(g_bmax[t][b])) / g_bsum[t][b];
}

// ---------------- pooling partials: block = (batch, slice), 512 thr --------
__global__ void k_pool(const float* __restrict__ x,
                       const float* __restrict__ g,
                       const float* __restrict__ be,
                       int t) {
    int b  = blockIdx.x >> 4;
    int sl = blockIdx.x & (SL - 1);
    int col = threadIdx.x;
    float gv = g[col], bev = be[col];
    int s0 = g_start[t][b], s1 = g_start[t][b + 1];
    int len = s1 - s0;
    int ps  = (len + SL - 1) / SL;
    int r0  = s0 + sl * ps;
    int r1  = min(r0 + ps, s1);

    float acc = 0.f, mx = -INFINITY;
    int n = r0;
    for (; n + 4 <= r1; n += 4) {
        float xv[4], a[4], c2[4];
        #pragma unroll
        for (int u = 0; u < 4; u++) xv[u] = x[(size_t)(n + u) * DD + col];
        #pragma unroll
        for (int u = 0; u < 4; u++) {
            float sn = g_sn[t][n + u];
            float mn = g_mean[t][n + u];
            float rs = g_rstd[t][n + u];
            a[u]  = rs * sn * gv;
            c2[u] = bev * sn - mn * a[u];
        }
        #pragma unroll
        for (int u = 0; u < 4; u++) {
            float xw = xv[u] * a[u] + c2[u];
            acc += xw;
            mx = fmaxf(mx, xw);
        }
    }
    for (; n < r1; n++) {
        float sn = g_sn[t][n];
        float aa = g_rstd[t][n] * sn * gv;
        float xw = x[(size_t)n * DD + col] * aa + bev * sn - g_mean[t][n] * aa;
        acc += xw;
        mx = fmaxf(mx, xw);
    }
    g_padd[t][b][sl][col] = acc;
    g_pmax[t][b][sl][col] = mx;
}

// ---------------- combine pool slices --------------------------------------
__global__ void k_pcomb() {
    int b = blockIdx.x, t = blockIdx.y;
    int col = threadIdx.x;
    float acc = 0.f, mx = -INFINITY;
    #pragma unroll
    for (int sl = 0; sl < SL; sl++) {
        acc += g_padd[t][b][sl][col];
        mx = fmaxf(mx, g_pmax[t][b][sl][col]);
    }
    g_add[t][b][col]  = acc;
    g_maxp[t][b][col] = mx;
}

// ---------------- MLP partial: grid (4 colchunks, 8 bgroups, KS) -----------
__global__ void k_mlp(const float* __restrict__ W, int t) {
    __shared__ float cat[8][256];
    int dchunk = blockIdx.x, bg = blockIdx.y, ks = blockIdx.z;
    const float (*src)[DD] = (ks < 2) ? g_add[t] : g_maxp[t];
    int koff = (ks & 1) * 256;
    int tid = threadIdx.x;
    for (int i = tid; i < 8 * 256; i += 128) {
        int bb = i >> 8, k = i & 255;
        cat[bb][k] = src[bg * 8 + bb][koff + k];
    }
    __syncthreads();

    int col = dchunk * 128 + tid;
    int kbase = ks * 256;
    float acc[8];
    #pragma unroll
    for (int bb = 0; bb < 8; bb++) acc[bb] = 0.f;

    for (int k = 0; k < 256; k += 4) {
        float w0 = W[(size_t)(kbase + k + 0) * DD + col];
        float w1 = W[(size_t)(kbase + k + 1) * DD + col];
        float w2 = W[(size_t)(kbase + k + 2) * DD + col];
        float w3 = W[(size_t)(kbase + k + 3) * DD + col];
        #pragma unroll
        for (int bb = 0; bb < 8; bb++) {
            const float4 c = reinterpret_cast<const float4*>(cat[bb])[k >> 2];
            acc[bb] += c.x * w0 + c.y * w1 + c.z * w2 + c.w * w3;
        }
    }
    #pragma unroll
    for (int bb = 0; bb < 8; bb++)
        g_mpart[t][ks][bg * 8 + bb][col] = acc[bb];
}

// ---------------- final combine + bias -------------------------------------
__global__ void k_out(const float* __restrict__ bmlp0,
                      const float* __restrict__ bmlp1,
                      float* __restrict__ out) {
    int b = blockIdx.x, t = blockIdx.y;
    int col = threadIdx.x;
    const float* bias = t ? bmlp1 : bmlp0;
    float v = bias[col];
    #pragma unroll
    for (int ks = 0; ks < KS; ks++) v += g_mpart[t][ks][b][col];
    out[b * (2 * DD) + t * DD + col] = v;
}

// ---------------- launch ----------------------------------------------------
extern "C" void kernel_launch(void* const* d_in, const int* in_sizes, int n_in,
                              void* d_out, int out_size) {
    const float* x_inst     = (const float*)d_in[0];
    const float* x_net      = (const float*)d_in[1];
    const float* ln_g_inst  = (const float*)d_in[2];
    const float* ln_b_inst  = (const float*)d_in[3];
    const float* ln_g_net   = (const float*)d_in[4];
    const float* ln_b_net   = (const float*)d_in[5];
    const float* Wkqv_inst  = (const float*)d_in[6];
    const float* bkqv_inst  = (const float*)d_in[7];
    const float* Wkqv_net   = (const float*)d_in[8];
    const float* bkqv_net   = (const float*)d_in[9];
    const float* k_rel_w    = (const float*)d_in[10];
    const float* k_rel_b    = (const float*)d_in[11];
    const float* v_rel_w    = (const float*)d_in[12];
    const float* v_rel_b    = (const float*)d_in[13];
    const float* p_rel      = (const float*)d_in[14];
    const float* w_out_inst = (const float*)d_in[15];
    const float* b_out_inst = (const float*)d_in[16];
    const float* w_out_net  = (const float*)d_in[17];
    const float* b_out_net  = (const float*)d_in[18];
    const float* W_mlp_inst = (const float*)d_in[19];
    const float* b_mlp_inst = (const float*)d_in[20];
    const float* W_mlp_net  = (const float*)d_in[21];
    const float* b_mlp_net  = (const float*)d_in[22];
    const int*   ei_i2n     = (const int*)d_in[23];
    const int*   ei_n2i     = (const int*)d_in[24];
    const int*   batch_inst = (const int*)d_in[25];
    const int*   batch_net  = (const int*)d_in[26];
    float* out = (float*)d_out;

    k_init<<<NN / 256, 256>>>();
    k_ln_kqv<<<NN / 8, 256>>>(x_inst, ln_g_inst, ln_b_inst, Wkqv_inst, bkqv_inst,
                              k_rel_w, k_rel_b, v_rel_w, v_rel_b, p_rel, 0);
    k_ln_kqv<<<NN / 8, 256>>>(x_net, ln_g_net, ln_b_net, Wkqv_net, bkqv_net,
                              k_rel_w, k_rel_b, v_rel_w, v_rel_b, p_rel, 1);
    k_starts<<<NN / 256, 256>>>(batch_inst, 0);
    k_starts<<<NN / 256, 256>>>(batch_net, 1);

    k_edge_max<<<dim3(EE / 1024, 2), 256>>>(ei_i2n, ei_n2i);
    k_edge_sum<<<dim3(EE / 1024, 2), 256>>>(ei_i2n, ei_n2i);

    k_score<<<NN / 256, 256>>>(w_out_inst, b_out_inst, batch_inst, 0);
    k_score<<<NN / 256, 256>>>(w_out_net,  b_out_net,  batch_net,  1);
    k_bsum<<<NN / 256, 256>>>(batch_inst, 0);
    k_bsum<<<NN / 256, 256>>>(batch_net, 1);
    k_sn<<<dim3(NN / 256, 2), 256>>>(batch_inst, batch_net);

    k_pool<<<BB * SL, 512>>>(x_inst, ln_g_inst, ln_b_inst, 0);
    k_pool<<<BB * SL, 512>>>(x_net,  ln_g_net,  ln_b_net,  1);
    k_pcomb<<<dim3(BB, 2), 512>>>();

    k_mlp<<<dim3(4, 8, KS), 128>>>(W_mlp_inst, 0);
    k_mlp<<<dim3(4, 8, KS), 128>>>(W_mlp_net, 1);
    k_out<<<dim3(BB, 2), 512>>>(b_mlp_inst, b_mlp_net, out);
}

// round 3
// speedup vs baseline: 4.3819x; 1.4172x over previous
#include <cuda_runtime.h>
#include <math.h>

#define NN 65536
#define EE 1048576
#define DD 512
#define BB 64
#define SL 16   // pool slices per batch
#define KS 4    // mlp k-splits

// ---------------- scratch (device globals; no allocations) ----------------
__device__ float    g_kt[2][NN];     // k * k_rel_w[rel] + k_rel_b[rel]
__device__ float    g_qp[2][NN];     // q * p_rel[rel_dst]
__device__ float    g_vt[2][NN];     // v * v_rel_w[rel] + v_rel_b[rel]
__device__ float    g_mean[2][NN];
__device__ float    g_rstd[2][NN];
__device__ float    g_s[2][NN];      // sum exp (edge softmax)
__device__ float    g_t[2][NN];      // sum exp * vt
__device__ float    g_score[2][NN];
__device__ float4   g_row[2][NN];    // packed pool params: {a2, sn, mean*a2, 0}
__device__ float    g_bsum[2][BB];
__device__ int      g_start[2][BB + 1];
__device__ float    g_padd[2][BB][SL][DD];
__device__ float    g_pmax[2][BB][SL][DD];
__device__ float    g_add[2][BB][DD];
__device__ float    g_maxp[2][BB][DD];
__device__ float    g_mpart[2][KS][BB][DD];

// ---------------- LayerNorm + kqv projection: warp-per-row, both tensors ---
// block = 256 threads = 8 rows; grid = (NN/8, 2)
__global__ void k_ln_kqv(const float* __restrict__ x0, const float* __restrict__ x1,
                         const float* __restrict__ g0, const float* __restrict__ g1,
                         const float* __restrict__ be0, const float* __restrict__ be1,
                         const float* __restrict__ W0, const float* __restrict__ W1,
                         const float* __restrict__ bk0, const float* __restrict__ bk1,
                         const float* __restrict__ krw, const float* __restrict__ krb,
                         const float* __restrict__ vrw, const float* __restrict__ vrb,
                         const float* __restrict__ prel) {
    int t = blockIdx.y;
    const float* x  = t ? x1 : x0;
    const float* g  = t ? g1 : g0;
    const float* be = t ? be1 : be0;
    const float* W  = t ? W1 : W0;
    const float* bk = t ? bk1 : bk0;

    __shared__ float sWT[3][DD];
    int tid = threadIdx.x;
    for (int i = tid; i < DD * 3; i += 256) sWT[i % 3][i / 3] = W[i];
    __syncthreads();

    int warp = tid >> 5, lane = tid & 31;
    int row  = blockIdx.x * 8 + warp;

    const float4* xr = reinterpret_cast<const float4*>(x + (size_t)row * DD);
    float4 xv[4];
    #pragma unroll
    for (int j = 0; j < 4; j++) xv[j] = xr[lane + 32 * j];

    float s = 0.f, ss = 0.f;
    #pragma unroll
    for (int j = 0; j < 4; j++) {
        s  += xv[j].x + xv[j].y + xv[j].z + xv[j].w;
        ss += xv[j].x * xv[j].x + xv[j].y * xv[j].y
            + xv[j].z * xv[j].z + xv[j].w * xv[j].w;
    }
    #pragma unroll
    for (int o = 16; o; o >>= 1) {
        s  += __shfl_xor_sync(0xffffffffu, s, o);
        ss += __shfl_xor_sync(0xffffffffu, ss, o);
    }
    float m   = s * (1.f / DD);
    float var = ss * (1.f / DD) - m * m;
    float r   = rsqrtf(var + 1e-5f);

    const float4* gr = reinterpret_cast<const float4*>(g);
    const float4* br = reinterpret_cast<const float4*>(be);
    const float4* w0p = reinterpret_cast<const float4*>(sWT[0]);
    const float4* w1p = reinterpret_cast<const float4*>(sWT[1]);
    const float4* w2p = reinterpret_cast<const float4*>(sWT[2]);

    float d0 = 0.f, d1 = 0.f, d2 = 0.f;
    #pragma unroll
    for (int j = 0; j < 4; j++) {
        int idx = lane + 32 * j;
        float4 gv = gr[idx], bv = br[idx];
        float a0 = (xv[j].x - m) * r * gv.x + bv.x;
        float a1 = (xv[j].y - m) * r * gv.y + bv.y;
        float a2 = (xv[j].z - m) * r * gv.z + bv.z;
        float a3 = (xv[j].w - m) * r * gv.w + bv.w;
        float4 w0 = w0p[idx], w1 = w1p[idx], w2 = w2p[idx];
        d0 += a0 * w0.x + a1 * w0.y + a2 * w0.z + a3 * w0.w;
        d1 += a0 * w1.x + a1 * w1.y + a2 * w1.z + a3 * w1.w;
        d2 += a0 * w2.x + a1 * w2.y + a2 * w2.z + a3 * w2.w;
    }
    #pragma unroll
    for (int o = 16; o; o >>= 1) {
        d0 += __shfl_xor_sync(0xffffffffu, d0, o);
        d1 += __shfl_xor_sync(0xffffffffu, d1, o);
        d2 += __shfl_xor_sync(0xffffffffu, d2, o);
    }
    if (lane == 0) {
        float kk = d0 + bk[0];
        float qq = d1 + bk[1];
        float vv = d2 + bk[2];
        g_kt[t][row]   = kk * krw[t] + krb[t];       // src rel = t
        g_qp[t][row]   = qq * prel[1 - t];           // dst rel = 1-t
        g_vt[t][row]   = vv * vrw[t] + vrb[t];
        g_mean[t][row] = m;
        g_rstd[t][row] = r;
        g_s[t][row]    = 0.f;                        // re-zero accumulators
        g_t[t][row]    = 0.f;
    }
}

// ---------------- batch segment starts + bsum zero (both tensors) ---------
__global__ void k_starts(const int* __restrict__ b0, const int* __restrict__ b1) {
    int t = blockIdx.y;
    const int* batch = t ? b1 : b0;
    int i = blockIdx.x * 256 + threadIdx.x;
    if (i < BB) g_bsum[t][i] = 0.f;
    if (i >= NN) return;
    int b = batch[i];
    int prev = (i == 0) ? -1 : batch[i - 1];
    for (int bb = prev + 1; bb <= b; bb++) g_start[t][bb] = i;
    if (i == NN - 1) {
        for (int bb = b + 1; bb <= BB; bb++) g_start[t][bb] = NN;
    }
}

// ---------------- edge attention: single pass, no max shift ----------------
// grid (EE/1024, 2); 4 edges/thread via int4
__global__ void k_edge(const int* __restrict__ ei0, const int* __restrict__ ei1) {
    int dir = blockIdx.y;
    const int* ei = dir ? ei1 : ei0;
    int ts = dir, td = 1 - dir;
    int e4 = blockIdx.x * 256 + threadIdx.x;
    int4 s4 = reinterpret_cast<const int4*>(ei)[e4];
    int4 d4 = reinterpret_cast<const int4*>(ei + EE)[e4];
    {
        float ex = __expf(g_qp[td][d4.x] * g_kt[ts][s4.x]);
        atomicAdd(&g_s[td][d4.x], ex);
        atomicAdd(&g_t[td][d4.x], ex * g_vt[ts][s4.x]);
    }
    {
        float ex = __expf(g_qp[td][d4.y] * g_kt[ts][s4.y]);
        atomicAdd(&g_s[td][d4.y], ex);
        atomicAdd(&g_t[td][d4.y], ex * g_vt[ts][s4.y]);
    }
    {
        float ex = __expf(g_qp[td][d4.z] * g_kt[ts][s4.z]);
        atomicAdd(&g_s[td][d4.z], ex);
        atomicAdd(&g_t[td][d4.z], ex * g_vt[ts][s4.z]);
    }
    {
        float ex = __expf(g_qp[td][d4.w] * g_kt[ts][s4.w]);
        atomicAdd(&g_s[td][d4.w], ex);
        atomicAdd(&g_t[td][d4.w], ex * g_vt[ts][s4.w]);
    }
}

// ---------------- score = gelu(aggr*w+b); bsum += exp(score) ---------------
__global__ void k_score(const float* __restrict__ w0, const float* __restrict__ bo0,
                        const float* __restrict__ w1, const float* __restrict__ bo1,
                        const int* __restrict__ batch0, const int* __restrict__ batch1) {
    int t = blockIdx.y;
    const float* wout = t ? w1 : w0;
    const float* bout = t ? bo1 : bo0;
    const int* batch  = t ? batch1 : batch0;
    int n = blockIdx.x * 256 + threadIdx.x;
    float ssum = g_s[t][n];
    float aggr = (ssum > 0.f) ? g_t[t][n] / ssum : 0.f;
    float xx = aggr * wout[0] + bout[0];
    float sc = 0.5f * xx * (1.f + erff(xx * 0.7071067811865475f));
    g_score[t][n] = sc;
    float ev = __expf(sc);
    int b = batch[n];
    int b0 = __shfl_sync(0xffffffffu, b, 0);
    if (__all_sync(0xffffffffu, b == b0)) {
        float sv = ev;
        #pragma unroll
        for (int o = 16; o; o >>= 1) sv += __shfl_xor_sync(0xffffffffu, sv, o);
        if ((threadIdx.x & 31) == 0) atomicAdd(&g_bsum[t][b], sv);
    } else {
        atomicAdd(&g_bsum[t][b], ev);
    }
}

// ---------------- per-node pool params (packed float4) ---------------------
__global__ void k_sn(const int* __restrict__ batch0, const int* __restrict__ batch1) {
    int t = blockIdx.y;
    const int* batch = t ? batch1 : batch0;
    int n = blockIdx.x * 256 + threadIdx.x;
    int b = batch[n];
    float sn = __expf(g_score[t][n]) / g_bsum[t][b];
    float a2 = g_rstd[t][n] * sn;
    g_row[t][n] = make_float4(a2, sn, g_mean[t][n] * a2, 0.f);
}

// ---------------- pooling partials: 128 thr, float4 cols -------------------
// grid (BB*SL, 2)
__global__ void k_pool(const float* __restrict__ x0, const float* __restrict__ x1,
                       const float* __restrict__ g0, const float* __restrict__ g1,
                       const float* __restrict__ be0, const float* __restrict__ be1) {
    int t  = blockIdx.y;
    const float* x  = t ? x1 : x0;
    const float* g  = t ? g1 : g0;
    const float* be = t ? be1 : be0;

    int b  = blockIdx.x >> 4;
    int sl = blockIdx.x & (SL - 1);
    int tid = threadIdx.x;
    float4 gv  = reinterpret_cast<const float4*>(g)[tid];
    float4 bev = reinterpret_cast<const float4*>(be)[tid];

    int s0 = g_start[t][b], s1 = g_start[t][b + 1];
    int len = s1 - s0;
    int ps  = (len + SL - 1) / SL;
    int r0  = s0 + sl * ps;
    int r1  = min(r0 + ps, s1);

    float4 acc = make_float4(0.f, 0.f, 0.f, 0.f);
    float4 mx  = make_float4(-INFINITY, -INFINITY, -INFINITY, -INFINITY);
    const float4* x4 = reinterpret_cast<const float4*>(x);

    int n = r0;
    for (; n + 4 <= r1; n += 4) {
        float4 xv[4], rp[4];
        #pragma unroll
        for (int u = 0; u < 4; u++) xv[u] = x4[(size_t)(n + u) * 128 + tid];
        #pragma unroll
        for (int u = 0; u < 4; u++) rp[u] = g_row[t][n + u];
        #pragma unroll
        for (int u = 0; u < 4; u++) {
            float w0 = gv.x * (xv[u].x * rp[u].x - rp[u].z) + bev.x * rp[u].y;
            float w1 = gv.y * (xv[u].y * rp[u].x - rp[u].z) + bev.y * rp[u].y;
            float w2 = gv.z * (xv[u].z * rp[u].x - rp[u].z) + bev.z * rp[u].y;
            float w3 = gv.w * (xv[u].w * rp[u].x - rp[u].z) + bev.w * rp[u].y;
            acc.x += w0; acc.y += w1; acc.z += w2; acc.w += w3;
            mx.x = fmaxf(mx.x, w0); mx.y = fmaxf(mx.y, w1);
            mx.z = fmaxf(mx.z, w2); mx.w = fmaxf(mx.w, w3);
        }
    }
    for (; n < r1; n++) {
        float4 xv = x4[(size_t)n * 128 + tid];
        float4 rp = g_row[t][n];
        float w0 = gv.x * (xv.x * rp.x - rp.z) + bev.x * rp.y;
        float w1 = gv.y * (xv.y * rp.x - rp.z) + bev.y * rp.y;
        float w2 = gv.z * (xv.z * rp.x - rp.z) + bev.z * rp.y;
        float w3 = gv.w * (xv.w * rp.x - rp.z) + bev.w * rp.y;
        acc.x += w0; acc.y += w1; acc.z += w2; acc.w += w3;
        mx.x = fmaxf(mx.x, w0); mx.y = fmaxf(mx.y, w1);
        mx.z = fmaxf(mx.z, w2); mx.w = fmaxf(mx.w, w3);
    }
    reinterpret_cast<float4*>(g_padd[t][b][sl])[tid] = acc;
    reinterpret_cast<float4*>(g_pmax[t][b][sl])[tid] = mx;
}

// ---------------- combine pool slices ---------------------------------------
__global__ void k_pcomb() {
    int b = blockIdx.x, t = blockIdx.y;
    int col = threadIdx.x;
    float acc = 0.f, mx = -INFINITY;
    #pragma unroll
    for (int sl = 0; sl < SL; sl++) {
        acc += g_padd[t][b][sl][col];
        mx = fmaxf(mx, g_pmax[t][b][sl][col]);
    }
    g_add[t][b][col]  = acc;
    g_maxp[t][b][col] = mx;
}

// ---------------- MLP partial: grid (4 colchunks, 8 bgroups, 2*KS) ----------
__global__ void k_mlp(const float* __restrict__ W0, const float* __restrict__ W1) {
    __shared__ float cat[8][256];
    int dchunk = blockIdx.x, bg = blockIdx.y;
    int t  = blockIdx.z >> 2;
    int ks = blockIdx.z & 3;
    const float* W = t ? W1 : W0;
    const float (*src)[DD] = (ks < 2) ? g_add[t] : g_maxp[t];
    int koff = (ks & 1) * 256;
    int tid = threadIdx.x;
    for (int i = tid; i < 8 * 256; i += 128) {
        int bb = i >> 8, k = i & 255;
        cat[bb][k] = src[bg * 8 + bb][koff + k];
    }
    __syncthreads();

    int col = dchunk * 128 + tid;
    int kbase = ks * 256;
    float acc[8];
    #pragma unroll
    for (int bb = 0; bb < 8; bb++) acc[bb] = 0.f;

    for (int k = 0; k < 256; k += 4) {
        float w0 = W[(size_t)(kbase + k + 0) * DD + col];
        float w1 = W[(size_t)(kbase + k + 1) * DD + col];
        float w2 = W[(size_t)(kbase + k + 2) * DD + col];
        float w3 = W[(size_t)(kbase + k + 3) * DD + col];
        #pragma unroll
        for (int bb = 0; bb < 8; bb++) {
            const float4 c = reinterpret_cast<const float4*>(cat[bb])[k >> 2];
            acc[bb] += c.x * w0 + c.y * w1 + c.z * w2 + c.w * w3;
        }
    }
    #pragma unroll
    for (int bb = 0; bb < 8; bb++)
        g_mpart[t][ks][bg * 8 + bb][col] = acc[bb];
}

// ---------------- final combine + bias ---------------------------------------
__global__ void k_out(const float* __restrict__ bmlp0,
                      const float* __restrict__ bmlp1,
                      float* __restrict__ out) {
    int b = blockIdx.x, t = blockIdx.y;
    int col = threadIdx.x;
    const float* bias = t ? bmlp1 : bmlp0;
    float v = bias[col];
    #pragma unroll
    for (int ks = 0; ks < KS; ks++) v += g_mpart[t][ks][b][col];
    out[b * (2 * DD) + t * DD + col] = v;
}

// ---------------- launch -----------------------------------------------------
extern "C" void kernel_launch(void* const* d_in, const int* in_sizes, int n_in,
                              void* d_out, int out_size) {
    const float* x_inst     = (const float*)d_in[0];
    const float* x_net      = (const float*)d_in[1];
    const float* ln_g_inst  = (const float*)d_in[2];
    const float* ln_b_inst  = (const float*)d_in[3];
    const float* ln_g_net   = (const float*)d_in[4];
    const float* ln_b_net   = (const float*)d_in[5];
    const float* Wkqv_inst  = (const float*)d_in[6];
    const float* bkqv_inst  = (const float*)d_in[7];
    const float* Wkqv_net   = (const float*)d_in[8];
    const float* bkqv_net   = (const float*)d_in[9];
    const float* k_rel_w    = (const float*)d_in[10];
    const float* k_rel_b    = (const float*)d_in[11];
    const float* v_rel_w    = (const float*)d_in[12];
    const float* v_rel_b    = (const float*)d_in[13];
    const float* p_rel      = (const float*)d_in[14];
    const float* w_out_inst = (const float*)d_in[15];
    const float* b_out_inst = (const float*)d_in[16];
    const float* w_out_net  = (const float*)d_in[17];
    const float* b_out_net  = (const float*)d_in[18];
    const float* W_mlp_inst = (const float*)d_in[19];
    const float* b_mlp_inst = (const float*)d_in[20];
    const float* W_mlp_net  = (const float*)d_in[21];
    const float* b_mlp_net  = (const float*)d_in[22];
    const int*   ei_i2n     = (const int*)d_in[23];
    const int*   ei_n2i     = (const int*)d_in[24];
    const int*   batch_inst = (const int*)d_in[25];
    const int*   batch_net  = (const int*)d_in[26];
    float* out = (float*)d_out;

    k_ln_kqv<<<dim3(NN / 8, 2), 256>>>(x_inst, x_net, ln_g_inst, ln_g_net,
                                       ln_b_inst, ln_b_net, Wkqv_inst, Wkqv_net,
                                       bkqv_inst, bkqv_net,
                                       k_rel_w, k_rel_b, v_rel_w, v_rel_b, p_rel);
    k_starts<<<dim3(NN / 256, 2), 256>>>(batch_inst, batch_net);
    k_edge<<<dim3(EE / 1024, 2), 256>>>(ei_i2n, ei_n2i);
    k_score<<<dim3(NN / 256, 2), 256>>>(w_out_inst, b_out_inst, w_out_net, b_out_net,
                                        batch_inst, batch_net);
    k_sn<<<dim3(NN / 256, 2), 256>>>(batch_inst, batch_net);
    k_pool<<<dim3(BB * SL, 2), 128>>>(x_inst, x_net, ln_g_inst, ln_g_net,
                                      ln_b_inst, ln_b_net);
    k_pcomb<<<dim3(BB, 2), 512>>>();
    k_mlp<<<dim3(4, 8, 2 * KS), 128>>>(W_mlp_inst, W_mlp_net);
    k_out<<<dim3(BB, 2), 512>>>(b_mlp_inst, b_mlp_net, out);
}

// round 5
// speedup vs baseline: 5.0485x; 1.1521x over previous
#include <cuda_runtime.h>
#include <cuda_fp16.h>
#include <math.h>

#define NN 65536
#define EE 1048576
#define DD 512
#define BB 64
#define SL 16   // pool slices per batch
#define KS 4    // mlp k-splits

// ---------------- fp16x2 bit-cast helpers ----------------
__device__ __forceinline__ unsigned h2u(__half2 h) {
    union { __half2 h; unsigned u; } c; c.h = h; return c.u;
}
__device__ __forceinline__ __half2 u2h(unsigned u) {
    union { unsigned u; __half2 h; } c; c.u = u; return c.h;
}

// ---------------- scratch (device globals; no allocations) ----------------
__device__ float2   g_kvt[2][NN];    // {kt, vt} packed for single gather
__device__ float    g_qp[2][NN];     // q * p_rel[rel_dst]
__device__ float2   g_st[2][NN];     // {sum exp, sum exp*vt} (adjacent atomics)
__device__ float    g_score[2][NN];
__device__ float    g_sn[2][NN];     // batch-softmax weight per node
__device__ float    g_bsum[2][BB];
__device__ int      g_start[2][BB + 1];
__device__ __half   g_xn[2][NN * DD];    // fp16 LN output cache (128 MB)
__device__ float    g_padd[2][BB][SL][DD];
__device__ float    g_pmax[2][BB][SL][DD];
__device__ float    g_add[2][BB][DD];
__device__ float    g_maxp[2][BB][DD];
__device__ float    g_mpart[2][KS][BB][DD];

// ---------------- LayerNorm + kqv projection: warp-per-row, both tensors ---
// block = 256 threads = 8 rows; grid = (NN/8, 2). Writes xn as fp16.
__global__ void k_ln_kqv(const float* __restrict__ x0, const float* __restrict__ x1,
                         const float* __restrict__ g0, const float* __restrict__ g1,
                         const float* __restrict__ be0, const float* __restrict__ be1,
                         const float* __restrict__ W0, const float* __restrict__ W1,
                         const float* __restrict__ bk0, const float* __restrict__ bk1,
                         const float* __restrict__ krw, const float* __restrict__ krb,
                         const float* __restrict__ vrw, const float* __restrict__ vrb,
                         const float* __restrict__ prel) {
    int t = blockIdx.y;
    const float* x  = t ? x1 : x0;
    const float* g  = t ? g1 : g0;
    const float* be = t ? be1 : be0;
    const float* W  = t ? W1 : W0;
    const float* bk = t ? bk1 : bk0;

    __shared__ float sWT[3][DD];
    int tid = threadIdx.x;
    for (int i = tid; i < DD * 3; i += 256) sWT[i % 3][i / 3] = W[i];
    __syncthreads();

    int warp = tid >> 5, lane = tid & 31;
    int row  = blockIdx.x * 8 + warp;

    const float4* xr = reinterpret_cast<const float4*>(x + (size_t)row * DD);
    float4 xv[4];
    #pragma unroll
    for (int j = 0; j < 4; j++) xv[j] = xr[lane + 32 * j];

    float s = 0.f, ss = 0.f;
    #pragma unroll
    for (int j = 0; j < 4; j++) {
        s  += xv[j].x + xv[j].y + xv[j].z + xv[j].w;
        ss += xv[j].x * xv[j].x + xv[j].y * xv[j].y
            + xv[j].z * xv[j].z + xv[j].w * xv[j].w;
    }
    #pragma unroll
    for (int o = 16; o; o >>= 1) {
        s  += __shfl_xor_sync(0xffffffffu, s, o);
        ss += __shfl_xor_sync(0xffffffffu, ss, o);
    }
    float m   = s * (1.f / DD);
    float var = ss * (1.f / DD) - m * m;
    float r   = rsqrtf(var + 1e-5f);

    const float4* gr = reinterpret_cast<const float4*>(g);
    const float4* br = reinterpret_cast<const float4*>(be);
    const float4* w0p = reinterpret_cast<const float4*>(sWT[0]);
    const float4* w1p = reinterpret_cast<const float4*>(sWT[1]);
    const float4* w2p = reinterpret_cast<const float4*>(sWT[2]);
    uint2* xnp = reinterpret_cast<uint2*>(g_xn[t] + (size_t)row * DD);

    float d0 = 0.f, d1 = 0.f, d2 = 0.f;
    #pragma unroll
    for (int j = 0; j < 4; j++) {
        int idx = lane + 32 * j;
        float4 gv = gr[idx], bv = br[idx];
        float a0 = (xv[j].x - m) * r * gv.x + bv.x;
        float a1 = (xv[j].y - m) * r * gv.y + bv.y;
        float a2 = (xv[j].z - m) * r * gv.z + bv.z;
        float a3 = (xv[j].w - m) * r * gv.w + bv.w;
        // cache xn as fp16
        uint2 pk;
        pk.x = h2u(__floats2half2_rn(a0, a1));
        pk.y = h2u(__floats2half2_rn(a2, a3));
        xnp[idx] = pk;
        float4 w0 = w0p[idx], w1 = w1p[idx], w2 = w2p[idx];
        d0 += a0 * w0.x + a1 * w0.y + a2 * w0.z + a3 * w0.w;
        d1 += a0 * w1.x + a1 * w1.y + a2 * w1.z + a3 * w1.w;
        d2 += a0 * w2.x + a1 * w2.y + a2 * w2.z + a3 * w2.w;
    }
    #pragma unroll
    for (int o = 16; o; o >>= 1) {
        d0 += __shfl_xor_sync(0xffffffffu, d0, o);
        d1 += __shfl_xor_sync(0xffffffffu, d1, o);
        d2 += __shfl_xor_sync(0xffffffffu, d2, o);
    }
    if (lane == 0) {
        float kk = d0 + bk[0];
        float qq = d1 + bk[1];
        float vv = d2 + bk[2];
        g_kvt[t][row] = make_float2(kk * krw[t] + krb[t],     // src rel = t
                                    vv * vrw[t] + vrb[t]);
        g_qp[t][row]  = qq * prel[1 - t];                     // dst rel = 1-t
        g_st[t][row]  = make_float2(0.f, 0.f);
    }
}

// ---------------- batch segment starts + bsum zero (both tensors) ---------
__global__ void k_starts(const int* __restrict__ b0, const int* __restrict__ b1) {
    int t = blockIdx.y;
    const int* batch = t ? b1 : b0;
    int i = blockIdx.x * 256 + threadIdx.x;
    if (i < BB) g_bsum[t][i] = 0.f;
    if (i >= NN) return;
    int b = batch[i];
    int prev = (i == 0) ? -1 : batch[i - 1];
    for (int bb = prev + 1; bb <= b; bb++) g_start[t][bb] = i;
    if (i == NN - 1) {
        for (int bb = b + 1; bb <= BB; bb++) g_start[t][bb] = NN;
    }
}

// ---------------- edge attention: single pass, no max shift ----------------
// grid (EE/1024, 2); 4 edges/thread via int4; 2 gathers + 2 adjacent atomics
__global__ void k_edge(const int* __restrict__ ei0, const int* __restrict__ ei1) {
    int dir = blockIdx.y;
    const int* ei = dir ? ei1 : ei0;
    int ts = dir, td = 1 - dir;
    int e4 = blockIdx.x * 256 + threadIdx.x;
    int4 s4 = reinterpret_cast<const int4*>(ei)[e4];
    int4 d4 = reinterpret_cast<const int4*>(ei + EE)[e4];
    {
        float2 kv = g_kvt[ts][s4.x];
        float ex = __expf(g_qp[td][d4.x] * kv.x);
        atomicAdd(&g_st[td][d4.x].x, ex);
        atomicAdd(&g_st[td][d4.x].y, ex * kv.y);
    }
    {
        float2 kv = g_kvt[ts][s4.y];
        float ex = __expf(g_qp[td][d4.y] * kv.x);
        atomicAdd(&g_st[td][d4.y].x, ex);
        atomicAdd(&g_st[td][d4.y].y, ex * kv.y);
    }
    {
        float2 kv = g_kvt[ts][s4.z];
        float ex = __expf(g_qp[td][d4.z] * kv.x);
        atomicAdd(&g_st[td][d4.z].x, ex);
        atomicAdd(&g_st[td][d4.z].y, ex * kv.y);
    }
    {
        float2 kv = g_kvt[ts][s4.w];
        float ex = __expf(g_qp[td][d4.w] * kv.x);
        atomicAdd(&g_st[td][d4.w].x, ex);
        atomicAdd(&g_st[td][d4.w].y, ex * kv.y);
    }
}

// ---------------- score = gelu(aggr*w+b); bsum += exp(score) ---------------
__global__ void k_score(const float* __restrict__ w0, const float* __restrict__ bo0,
                        const float* __restrict__ w1, const float* __restrict__ bo1,
                        const int* __restrict__ batch0, const int* __restrict__ batch1) {
    int t = blockIdx.y;
    const float* wout = t ? w1 : w0;
    const float* bout = t ? bo1 : bo0;
    const int* batch  = t ? batch1 : batch0;
    int n = blockIdx.x * 256 + threadIdx.x;
    float2 st = g_st[t][n];
    float aggr = (st.x > 0.f) ? st.y / st.x : 0.f;
    float xx = aggr * wout[0] + bout[0];
    float sc = 0.5f * xx * (1.f + erff(xx * 0.7071067811865475f));
    g_score[t][n] = sc;
    float ev = __expf(sc);
    int b = batch[n];
    int b0 = __shfl_sync(0xffffffffu, b, 0);
    if (__all_sync(0xffffffffu, b == b0)) {
        float sv = ev;
        #pragma unroll
        for (int o = 16; o; o >>= 1) sv += __shfl_xor_sync(0xffffffffu, sv, o);
        if ((threadIdx.x & 31) == 0) atomicAdd(&g_bsum[t][b], sv);
    } else {
        atomicAdd(&g_bsum[t][b], ev);
    }
}

// ---------------- per-node pool weight --------------------------------------
__global__ void k_sn(const int* __restrict__ batch0, const int* __restrict__ batch1) {
    int t = blockIdx.y;
    const int* batch = t ? batch1 : batch0;
    int n = blockIdx.x * 256 + threadIdx.x;
    int b = batch[n];
    g_sn[t][n] = __expf(g_score[t][n]) / g_bsum[t][b];
}

// ---------------- pooling partials from fp16 xn: 128 thr, 4 cols each ------
// grid (BB*SL, 2)
__global__ void k_pool() {
    int t  = blockIdx.y;
    int b  = blockIdx.x >> 4;
    int sl = blockIdx.x & (SL - 1);
    int tid = threadIdx.x;

    int s0 = g_start[t][b], s1 = g_start[t][b + 1];
    int len = s1 - s0;
    int ps  = (len + SL - 1) / SL;
    int r0  = s0 + sl * ps;
    int r1  = min(r0 + ps, s1);

    float4 acc = make_float4(0.f, 0.f, 0.f, 0.f);
    float4 mx  = make_float4(-INFINITY, -INFINITY, -INFINITY, -INFINITY);
    const uint2* xn4 = reinterpret_cast<const uint2*>(g_xn[t]);

    int n = r0;
    for (; n + 8 <= r1; n += 8) {
        uint2 pk[8];
        float sn[8];
        #pragma unroll
        for (int u = 0; u < 8; u++) pk[u] = xn4[(size_t)(n + u) * 128 + tid];
        #pragma unroll
        for (int u = 0; u < 8; u++) sn[u] = g_sn[t][n + u];
        #pragma unroll
        for (int u = 0; u < 8; u++) {
            float2 lo = __half22float2(u2h(pk[u].x));
            float2 hi = __half22float2(u2h(pk[u].y));
            float w0 = lo.x * sn[u], w1 = lo.y * sn[u];
            float w2 = hi.x * sn[u], w3 = hi.y * sn[u];
            acc.x += w0; acc.y += w1; acc.z += w2; acc.w += w3;
            mx.x = fmaxf(mx.x, w0); mx.y = fmaxf(mx.y, w1);
            mx.z = fmaxf(mx.z, w2); mx.w = fmaxf(mx.w, w3);
        }
    }
    for (; n < r1; n++) {
        uint2 pk = xn4[(size_t)n * 128 + tid];
        float sn = g_sn[t][n];
        float2 lo = __half22float2(u2h(pk.x));
        float2 hi = __half22float2(u2h(pk.y));
        float w0 = lo.x * sn, w1 = lo.y * sn;
        float w2 = hi.x * sn, w3 = hi.y * sn;
        acc.x += w0; acc.y += w1; acc.z += w2; acc.w += w3;
        mx.x = fmaxf(mx.x, w0); mx.y = fmaxf(mx.y, w1);
        mx.z = fmaxf(mx.z, w2); mx.w = fmaxf(mx.w, w3);
    }
    reinterpret_cast<float4*>(g_padd[t][b][sl])[tid] = acc;
    reinterpret_cast<float4*>(g_pmax[t][b][sl])[tid] = mx;
}

// ---------------- combine pool slices ---------------------------------------
__global__ void k_pcomb() {
    int b = blockIdx.x, t = blockIdx.y;
    int col = threadIdx.x;
    float acc = 0.f, mx = -INFINITY;
    #pragma unroll
    for (int sl = 0; sl < SL; sl++) {
        acc += g_padd[t][b][sl][col];
        mx = fmaxf(mx, g_pmax[t][b][sl][col]);
    }
    g_add[t][b][col]  = acc;
    g_maxp[t][b][col] = mx;
}

// ---------------- MLP partial: grid (4 colchunks, 8 bgroups, 2*KS) ----------
__global__ void k_mlp(const float* __restrict__ W0, const float* __restrict__ W1) {
    __shared__ float cat[8][256];
    int dchunk = blockIdx.x, bg = blockIdx.y;
    int t  = blockIdx.z >> 2;
    int ks = blockIdx.z & 3;
    const float* W = t ? W1 : W0;
    const float (*src)[DD] = (ks < 2) ? g_add[t] : g_maxp[t];
    int koff = (ks & 1) * 256;
    int tid = threadIdx.x;
    for (int i = tid; i < 8 * 256; i += 128) {
        int bb = i >> 8, k = i & 255;
        cat[bb][k] = src[bg * 8 + bb][koff + k];
    }
    __syncthreads();

    int col = dchunk * 128 + tid;
    int kbase = ks * 256;
    float acc[8];
    #pragma unroll
    for (int bb = 0; bb < 8; bb++) acc[bb] = 0.f;

    for (int k = 0; k < 256; k += 4) {
        float w0 = W[(size_t)(kbase + k + 0) * DD + col];
        float w1 = W[(size_t)(kbase + k + 1) * DD + col];
        float w2 = W[(size_t)(kbase + k + 2) * DD + col];
        float w3 = W[(size_t)(kbase + k + 3) * DD + col];
        #pragma unroll
        for (int bb = 0; bb < 8; bb++) {
            const float4 c = reinterpret_cast<const float4*>(cat[bb])[k >> 2];
            acc[bb] += c.x * w0 + c.y * w1 + c.z * w2 + c.w * w3;
        }
    }
    #pragma unroll
    for (int bb = 0; bb < 8; bb++)
        g_mpart[t][ks][bg * 8 + bb][col] = acc[bb];
}

// ---------------- final combine + bias ---------------------------------------
__global__ void k_out(const float* __restrict__ bmlp0,
                      const float* __restrict__ bmlp1,
                      float* __restrict__ out) {
    int b = blockIdx.x, t = blockIdx.y;
    int col = threadIdx.x;
    const float* bias = t ? bmlp1 : bmlp0;
    float v = bias[col];
    #pragma unroll
    for (int ks = 0; ks < KS; ks++) v += g_mpart[t][ks][b][col];
    out[b * (2 * DD) + t * DD + col] = v;
}

// ---------------- launch -----------------------------------------------------
extern "C" void kernel_launch(void* const* d_in, const int* in_sizes, int n_in,
                              void* d_out, int out_size) {
    const float* x_inst     = (const float*)d_in[0];
    const float* x_net      = (const float*)d_in[1];
    const float* ln_g_inst  = (const float*)d_in[2];
    const float* ln_b_inst  = (const float*)d_in[3];
    const float* ln_g_net   = (const float*)d_in[4];
    const float* ln_b_net   = (const float*)d_in[5];
    const float* Wkqv_inst  = (const float*)d_in[6];
    const float* bkqv_inst  = (const float*)d_in[7];
    const float* Wkqv_net   = (const float*)d_in[8];
    const float* bkqv_net   = (const float*)d_in[9];
    const float* k_rel_w    = (const float*)d_in[10];
    const float* k_rel_b    = (const float*)d_in[11];
    const float* v_rel_w    = (const float*)d_in[12];
    const float* v_rel_b    = (const float*)d_in[13];
    const float* p_rel      = (const float*)d_in[14];
    const float* w_out_inst = (const float*)d_in[15];
    const float* b_out_inst = (const float*)d_in[16];
    const float* w_out_net  = (const float*)d_in[17];
    const float* b_out_net  = (const float*)d_in[18];
    const float* W_mlp_inst = (const float*)d_in[19];
    const float* b_mlp_inst = (const float*)d_in[20];
    const float* W_mlp_net  = (const float*)d_in[21];
    const float* b_mlp_net  = (const float*)d_in[22];
    const int*   ei_i2n     = (const int*)d_in[23];
    const int*   ei_n2i     = (const int*)d_in[24];
    const int*   batch_inst = (const int*)d_in[25];
    const int*   batch_net  = (const int*)d_in[26];
    float* out = (float*)d_out;

    k_ln_kqv<<<dim3(NN / 8, 2), 256>>>(x_inst, x_net, ln_g_inst, ln_g_net,
                                       ln_b_inst, ln_b_net, Wkqv_inst, Wkqv_net,
                                       bkqv_inst, bkqv_net,
                                       k_rel_w, k_rel_b, v_rel_w, v_rel_b, p_rel);
    k_starts<<<dim3(NN / 256, 2), 256>>>(batch_inst, batch_net);
    k_edge<<<dim3(EE / 1024, 2), 256>>>(ei_i2n, ei_n2i);
    k_score<<<dim3(NN / 256, 2), 256>>>(w_out_inst, b_out_inst, w_out_net, b_out_net,
                                        batch_inst, batch_net);
    k_sn<<<dim3(NN / 256, 2), 256>>>(batch_inst, batch_net);
    k_pool<<<dim3(BB * SL, 2), 128>>>();
    k_pcomb<<<dim3(BB, 2), 512>>>();
    k_mlp<<<dim3(4, 8, 2 * KS), 128>>>(W_mlp_inst, W_mlp_net);
    k_out<<<dim3(BB, 2), 512>>>(b_mlp_inst, b_mlp_net, out);
}